// round 2
// baseline (speedup 1.0000x reference)
#include <cuda_runtime.h>
#include <cuda_bf16.h>
#include <stdint.h>

#define BB 512
#define TT 256
#define HH 256
#define HORZ 22
#define ROWS 8      // batch rows per cluster
#define COLSK 128   // hidden columns per CTA (cluster of 2 covers 256)
#define NTHREADS 256

// shared memory byte offsets (dynamic smem, one CTA)
#define OFF_UZ   0          // bf16 [256][128] = 65536
#define OFF_UR   65536
#define OFF_UH   131072
#define OFF_HT   196608     // f32 [256][8] = 8192   (hT[k][r], replicated per CTA)
#define OFF_RHT  204800     // f32 [256][8] = 8192   (r*h, replicated per CTA)
#define OFF_XST  212992     // f32 [256][8] = 8192   (x[t][r])
#define OFF_GST  221184     // f32 [256][8] = 8192   (garch_in[t][r])
#define OFF_WV   229376     // bf16 8*[128] = 2048   (wz,bz,wr,br,wh,bh,wg,wgb slices)
#define SMEM_BYTES 231424

__device__ float g_h[BB * HH];   // final hidden state scratch (allowed: __device__ global)

__device__ __forceinline__ float fsig(float x) { return 1.0f / (1.0f + __expf(-x)); }
__device__ __forceinline__ float ftanha(float x) {
    float y; asm("tanh.approx.f32 %0, %1;" : "=f"(y) : "f"(x)); return y;
}
__device__ __forceinline__ uint32_t s2u(const void* p) {
    return (uint32_t)__cvta_generic_to_shared(p);
}
__device__ __forceinline__ uint32_t mapa32(uint32_t a, uint32_t r) {
    uint32_t d; asm("mapa.shared::cluster.u32 %0, %1, %2;" : "=r"(d) : "r"(a), "r"(r)); return d;
}
__device__ __forceinline__ void st_dsm(uint32_t a, float v) {
    asm volatile("st.shared::cluster.f32 [%0], %1;" :: "r"(a), "f"(v) : "memory");
}
__device__ __forceinline__ void csync() {
    asm volatile("barrier.cluster.arrive.aligned;" ::: "memory");
    asm volatile("barrier.cluster.wait.aligned;" ::: "memory");
}

extern "C" __global__ __launch_bounds__(NTHREADS, 1) __cluster_dims__(2, 1, 1)
void garch_gru_recur(const float* __restrict__ x,
                     const float* __restrict__ Wzw, const float* __restrict__ Wzb,
                     const float* __restrict__ Uzw, const float* __restrict__ Uzb,
                     const float* __restrict__ Wrw, const float* __restrict__ Wrb,
                     const float* __restrict__ Urw, const float* __restrict__ Urb,
                     const float* __restrict__ Whw, const float* __restrict__ Whb,
                     const float* __restrict__ Uhw, const float* __restrict__ Uhb,
                     const float* __restrict__ Wgw, const float* __restrict__ Wgb,
                     const float* __restrict__ omega_raw, const float* __restrict__ alpha_raw,
                     const float* __restrict__ beta_raw,  const float* __restrict__ gamma_p,
                     float* __restrict__ sig_out)
{
    extern __shared__ char smem[];
    __nv_bfloat16* Uzs = (__nv_bfloat16*)(smem + OFF_UZ);
    __nv_bfloat16* Urs = (__nv_bfloat16*)(smem + OFF_UR);
    __nv_bfloat16* Uhs = (__nv_bfloat16*)(smem + OFF_UH);
    float* hT  = (float*)(smem + OFF_HT);
    float* rhT = (float*)(smem + OFF_RHT);
    float* xsT = (float*)(smem + OFF_XST);
    float* gsT = (float*)(smem + OFF_GST);
    __nv_bfloat16* wv = (__nv_bfloat16*)(smem + OFF_WV);

    const int tid = threadIdx.x;
    uint32_t rank; asm("mov.u32 %0, %%cluster_ctarank;" : "=r"(rank));
    const int rbase = (int)(blockIdx.x >> 1) * ROWS;   // batch rows of this cluster
    const int cb = (int)rank * COLSK;                  // hidden-column base of this CTA
    const int col = tid & (COLSK - 1);                 // local hidden column owned
    const int r0 = (tid >> 7) << 2;                    // rows r0..r0+3 handled

    // ---- load weight slices (bf16) ----
    for (int idx = tid; idx < HH * COLSK; idx += NTHREADS) {
        int k = idx >> 7, j = idx & (COLSK - 1);
        int g = k * HH + cb + j;
        Uzs[idx] = __float2bfloat16(Uzw[g]);
        Urs[idx] = __float2bfloat16(Urw[g]);
        Uhs[idx] = __float2bfloat16(Uhw[g]);
    }
    if (tid < COLSK) {
        int g = cb + tid;
        wv[0*COLSK+tid] = __float2bfloat16(Wzw[g]);
        wv[1*COLSK+tid] = __float2bfloat16(Wzb[g] + Uzb[g]);   // fused biases
        wv[2*COLSK+tid] = __float2bfloat16(Wrw[g]);
        wv[3*COLSK+tid] = __float2bfloat16(Wrb[g] + Urb[g]);
        wv[4*COLSK+tid] = __float2bfloat16(Whw[g]);
        wv[5*COLSK+tid] = __float2bfloat16(Whb[g] + Uhb[g]);
        wv[6*COLSK+tid] = __float2bfloat16(Wgw[g]);
        wv[7*COLSK+tid] = __float2bfloat16(Wgb[g]);
    }
    // ---- x tile (fp32, exact: feeds GARCH) ----
    for (int idx = tid; idx < ROWS * TT; idx += NTHREADS) {
        int r = idx >> 8, t = idx & (TT - 1);
        xsT[t * ROWS + r] = x[(rbase + r) * TT + t];
    }
    for (int idx = tid; idx < HH * ROWS; idx += NTHREADS) hT[idx] = 0.0f;
    __syncthreads();

    // ---- GARCH precompute (exact fp32; independent of GRU) ----
    if (tid < ROWS) {
        float orw = omega_raw[0];
        float om = ((orw > 20.0f) ? orw : log1pf(expf(orw))) + 1e-6f;
        float av = 1.0f / (1.0f + expf(-alpha_raw[0]));
        float bv = (1.0f / (1.0f + expf(-beta_raw[0]))) * (1.0f - av * 0.99f);
        float es = 1e-6f, ss = 1e-6f;
        for (int t = 0; t < TT; t++) {
            float g = om + av * es + bv * ss;
            gsT[t * ROWS + tid] = g;
            float e = xsT[t * ROWS + tid];
            es = e * e; ss = g;
        }
        if (rank == 0) sig_out[rbase + tid] = ss;   // sigma_sq output (exact)
    }

    const float gamma = gamma_p[0];
    const uint32_t peer = rank ^ 1u;
    const uint32_t rh_peer = mapa32(s2u(&rhT[col * ROWS + r0]), peer);
    const uint32_t h_peer  = mapa32(s2u(&hT [col * ROWS + r0]), peer);

    csync();   // gsT visible intra-CTA; symmetric barrier count starts here

    const float wzc = __bfloat162float(wv[0*COLSK+col]);
    const float bzc = __bfloat162float(wv[1*COLSK+col]);
    const float wrc = __bfloat162float(wv[2*COLSK+col]);
    const float brc = __bfloat162float(wv[3*COLSK+col]);
    const float whc = __bfloat162float(wv[4*COLSK+col]);
    const float bhc = __bfloat162float(wv[5*COLSK+col]);
    const float wgc = __bfloat162float(wv[6*COLSK+col]);
    const float wgbc= __bfloat162float(wv[7*COLSK+col]);

    for (int t = 0; t < TT; t++) {
        const float4 xv = *(const float4*)&xsT[t * ROWS + r0];

        // ---- phase A: z and r gates for (rows r0..r0+3, col) ----
        float az0 = fmaf(xv.x, wzc, bzc), az1 = fmaf(xv.y, wzc, bzc);
        float az2 = fmaf(xv.z, wzc, bzc), az3 = fmaf(xv.w, wzc, bzc);
        float ar0 = fmaf(xv.x, wrc, brc), ar1 = fmaf(xv.y, wrc, brc);
        float ar2 = fmaf(xv.z, wrc, brc), ar3 = fmaf(xv.w, wrc, brc);
        #pragma unroll 8
        for (int k = 0; k < HH; k++) {
            const float4 hv = *(const float4*)&hT[k * ROWS + r0];   // LDS.128 broadcast
            const float uz = __bfloat162float(Uzs[k * COLSK + col]);
            const float ur = __bfloat162float(Urs[k * COLSK + col]);
            az0 = fmaf(hv.x, uz, az0); az1 = fmaf(hv.y, uz, az1);
            az2 = fmaf(hv.z, uz, az2); az3 = fmaf(hv.w, uz, az3);
            ar0 = fmaf(hv.x, ur, ar0); ar1 = fmaf(hv.y, ur, ar1);
            ar2 = fmaf(hv.z, ur, ar2); ar3 = fmaf(hv.w, ur, ar3);
        }
        const float4 hold = *(const float4*)&hT[col * ROWS + r0];   // own column, old h
        const float z0 = fsig(az0), z1 = fsig(az1), z2 = fsig(az2), z3 = fsig(az3);
        const float rh0 = fsig(ar0) * hold.x, rh1 = fsig(ar1) * hold.y;
        const float rh2 = fsig(ar2) * hold.z, rh3 = fsig(ar3) * hold.w;
        *(float4*)&rhT[col * ROWS + r0] = make_float4(rh0, rh1, rh2, rh3);
        st_dsm(rh_peer + 0, rh0); st_dsm(rh_peer + 4, rh1);
        st_dsm(rh_peer + 8, rh2); st_dsm(rh_peer + 12, rh3);
        csync();   // r*h complete in both CTAs

        // ---- phase B: h_tilde and combine ----
        float ah0 = fmaf(xv.x, whc, bhc), ah1 = fmaf(xv.y, whc, bhc);
        float ah2 = fmaf(xv.z, whc, bhc), ah3 = fmaf(xv.w, whc, bhc);
        #pragma unroll 8
        for (int k = 0; k < HH; k++) {
            const float4 rv = *(const float4*)&rhT[k * ROWS + r0];
            const float uh = __bfloat162float(Uhs[k * COLSK + col]);
            ah0 = fmaf(rv.x, uh, ah0); ah1 = fmaf(rv.y, uh, ah1);
            ah2 = fmaf(rv.z, uh, ah2); ah3 = fmaf(rv.w, uh, ah3);
        }
        const float4 gv = *(const float4*)&gsT[t * ROWS + r0];
        const float gt0 = fmaf(gv.x, wgc, wgbc), gt1 = fmaf(gv.y, wgc, wgbc);
        const float gt2 = fmaf(gv.z, wgc, wgbc), gt3 = fmaf(gv.w, wgc, wgbc);
        const float hn0 = ftanha(fmaf(1.0f - z0, ftanha(ah0), z0 * hold.x) + gamma * gt0);
        const float hn1 = ftanha(fmaf(1.0f - z1, ftanha(ah1), z1 * hold.y) + gamma * gt1);
        const float hn2 = ftanha(fmaf(1.0f - z2, ftanha(ah2), z2 * hold.z) + gamma * gt2);
        const float hn3 = ftanha(fmaf(1.0f - z3, ftanha(ah3), z3 * hold.w) + gamma * gt3);
        *(float4*)&hT[col * ROWS + r0] = make_float4(hn0, hn1, hn2, hn3);
        st_dsm(h_peer + 0, hn0); st_dsm(h_peer + 4, hn1);
        st_dsm(h_peer + 8, hn2); st_dsm(h_peer + 12, hn3);
        csync();   // h complete in both CTAs -> next step
    }

    // ---- write final h (own columns only; coalesced across lanes) ----
    #pragma unroll
    for (int i = 0; i < 4; i++)
        g_h[(rbase + r0 + i) * HH + cb + col] = hT[col * ROWS + r0 + i];
}

// ---- final head: hid = relu(h@fc1+b); vol = clip(vol_base*(1+softplus(hid@fc2+b))) ----
extern "C" __global__ __launch_bounds__(256)
void garch_gru_head(const float* __restrict__ fc1w, const float* __restrict__ fc1b,
                    const float* __restrict__ fc2w, const float* __restrict__ fc2b,
                    float* __restrict__ out, int sig_off)
{
    __shared__ float hs[HH];
    __shared__ float hid[HH];
    const int row = blockIdx.x;
    const int tid = threadIdx.x;
    hs[tid] = g_h[row * HH + tid];
    __syncthreads();
    float acc = fc1b[tid];
    #pragma unroll 8
    for (int k = 0; k < HH; k++) acc = fmaf(hs[k], fc1w[k * HH + tid], acc);
    hid[tid] = fmaxf(acc, 0.0f);
    __syncthreads();
    if (tid < HORZ) {
        float u = fc2b[tid];
        #pragma unroll 8
        for (int j = 0; j < HH; j++) u = fmaf(hid[j], fc2w[j * HORZ + tid], u);
        const float sp = (u > 20.0f) ? u : log1pf(expf(u));
        const float ssq = out[sig_off + row];          // written by recur kernel
        const float vb = sqrtf(ssq + 1e-8f);
        float v = vb * (1.0f + sp);
        v = fminf(fmaxf(v, 0.01f), 10.0f);
        out[row * HORZ + tid] = v;
    }
}

extern "C" void kernel_launch(void* const* d_in, const int* in_sizes, int n_in,
                              void* d_out, int out_size) {
    const float* x    = (const float*)d_in[0];
    const float* Wzw  = (const float*)d_in[1];
    const float* Wzb  = (const float*)d_in[2];
    const float* Uzw  = (const float*)d_in[3];
    const float* Uzb  = (const float*)d_in[4];
    const float* Wrw  = (const float*)d_in[5];
    const float* Wrb  = (const float*)d_in[6];
    const float* Urw  = (const float*)d_in[7];
    const float* Urb  = (const float*)d_in[8];
    const float* Whw  = (const float*)d_in[9];
    const float* Whb  = (const float*)d_in[10];
    const float* Uhw  = (const float*)d_in[11];
    const float* Uhb  = (const float*)d_in[12];
    const float* Wgw  = (const float*)d_in[13];
    const float* Wgb  = (const float*)d_in[14];
    const float* omr  = (const float*)d_in[15];
    const float* alr  = (const float*)d_in[16];
    const float* ber  = (const float*)d_in[17];
    const float* gam  = (const float*)d_in[18];
    const float* fc1w = (const float*)d_in[19];
    const float* fc1b = (const float*)d_in[20];
    const float* fc2w = (const float*)d_in[21];
    const float* fc2b = (const float*)d_in[22];
    float* out = (float*)d_out;
    const int sig_off = out_size - BB;   // vol[B,HOR] then sigma_sq[B]

    cudaFuncSetAttribute(garch_gru_recur,
                         cudaFuncAttributeMaxDynamicSharedMemorySize, SMEM_BYTES);
    garch_gru_recur<<<(BB / ROWS) * 2, NTHREADS, SMEM_BYTES>>>(
        x, Wzw, Wzb, Uzw, Uzb, Wrw, Wrb, Urw, Urb, Whw, Whb, Uhw, Uhb, Wgw, Wgb,
        omr, alr, ber, gam, out + sig_off);
    garch_gru_head<<<BB, 256>>>(fc1w, fc1b, fc2w, fc2b, out, sig_off);
}

// round 6
// speedup vs baseline: 1.1269x; 1.1269x over previous
#include <cuda_runtime.h>
#include <cuda_bf16.h>
#include <stdint.h>

#define BB 512
#define TT 256
#define HH 256
#define HORZ 22
#define ROWS 8      // batch rows per cluster
#define COLSK 128   // hidden columns per CTA (cluster of 2 covers 256)
#define NTH 256

// dynamic smem layout (bytes)
#define OFF_WZR 0          // u32  [256][128] : packed (bf16 Uz | bf16 Ur<<16) = 131072
#define OFF_UH  131072     // bf16 [256][128] = 65536
#define OFF_HT  196608     // f32  [256][8]   = 8192   hT[k][r]
#define OFF_RHT 204800     // f32  [256][8]   = 8192   (r*h)[k][r]
#define OFF_XST 212992     // f32  [256][8]   = 8192   x[t][r]
#define OFF_WV  221184     // f32  [8][128]   = 4096   per-col scalars
#define SMEM_BYTES 225280

__device__ float g_h[BB * HH];   // final hidden state scratch

typedef unsigned long long u64;

__device__ __forceinline__ float ftanha(float x) {
    float y; asm("tanh.approx.f32 %0, %1;" : "=f"(y) : "f"(x)); return y;
}
__device__ __forceinline__ float fsig(float x) {            // sigmoid via 1 MUFU
    return fmaf(0.5f, ftanha(0.5f * x), 0.5f);
}
__device__ __forceinline__ u64 dupf(float v) {
    u64 r; asm("mov.b64 %0, {%1,%1};" : "=l"(r) : "f"(v)); return r;
}
__device__ __forceinline__ u64 dupu(uint32_t v) {
    u64 r; asm("mov.b64 %0, {%1,%1};" : "=l"(r) : "r"(v)); return r;
}
__device__ __forceinline__ void fma2(u64& d, u64 a, u64 b) {
    asm("fma.rn.f32x2 %0, %1, %2, %0;" : "+l"(d) : "l"(a), "l"(b));
}
__device__ __forceinline__ float2 unp(u64 v) {
    float2 f; asm("mov.b64 {%0,%1}, %2;" : "=f"(f.x), "=f"(f.y) : "l"(v)); return f;
}
__device__ __forceinline__ uint32_t s2u(const void* p) {
    return (uint32_t)__cvta_generic_to_shared(p);
}
__device__ __forceinline__ uint32_t mapa32(uint32_t a, uint32_t r) {
    uint32_t d; asm("mapa.shared::cluster.u32 %0, %1, %2;" : "=r"(d) : "r"(a), "r"(r)); return d;
}
__device__ __forceinline__ void st_dsm(uint32_t a, float v) {
    asm volatile("st.shared::cluster.f32 [%0], %1;" :: "r"(a), "f"(v) : "memory");
}
__device__ __forceinline__ void c_arrive() {
    asm volatile("barrier.cluster.arrive.aligned;" ::: "memory");
}
__device__ __forceinline__ void c_wait() {
    asm volatile("barrier.cluster.wait.aligned;" ::: "memory");
}
__device__ __forceinline__ uint16_t bfb(float v) {
    return __bfloat16_as_ushort(__float2bfloat16(v));
}

extern "C" __global__ __launch_bounds__(NTH, 1) __cluster_dims__(2, 1, 1)
void garch_gru_recur(const float* __restrict__ x,
                     const float* __restrict__ Wzw, const float* __restrict__ Wzb,
                     const float* __restrict__ Uzw, const float* __restrict__ Uzb,
                     const float* __restrict__ Wrw, const float* __restrict__ Wrb,
                     const float* __restrict__ Urw, const float* __restrict__ Urb,
                     const float* __restrict__ Whw, const float* __restrict__ Whb,
                     const float* __restrict__ Uhw, const float* __restrict__ Uhb,
                     const float* __restrict__ Wgw, const float* __restrict__ Wgb,
                     const float* __restrict__ omega_raw, const float* __restrict__ alpha_raw,
                     const float* __restrict__ beta_raw,  const float* __restrict__ gamma_p,
                     float* __restrict__ sig_out)
{
    extern __shared__ char smem[];
    uint32_t* WZR = (uint32_t*)(smem + OFF_WZR);
    uint16_t* UHs = (uint16_t*)(smem + OFF_UH);
    float* hT  = (float*)(smem + OFF_HT);
    float* rhT = (float*)(smem + OFF_RHT);
    float* xsT = (float*)(smem + OFF_XST);
    float* wv  = (float*)(smem + OFF_WV);

    const int tid = threadIdx.x;
    uint32_t rank; asm("mov.u32 %0, %%cluster_ctarank;" : "=r"(rank));
    const int rbase = (int)(blockIdx.x >> 1) * ROWS;
    const int cb = (int)rank * COLSK;
    const int col = tid & (COLSK - 1);
    const int r0 = (tid >> 7) << 2;          // 0 or 4

    // ---- pack weight slices ----
    for (int idx = tid; idx < HH * COLSK; idx += NTH) {
        int k = idx >> 7, j = idx & (COLSK - 1);
        int g = k * HH + cb + j;
        WZR[idx] = (uint32_t)bfb(Uzw[g]) | ((uint32_t)bfb(Urw[g]) << 16);
        UHs[idx] = bfb(Uhw[g]);
    }
    if (tid < COLSK) {
        int g = cb + tid;
        wv[0*COLSK+tid] = Wzw[g];
        wv[1*COLSK+tid] = Wzb[g] + Uzb[g];
        wv[2*COLSK+tid] = Wrw[g];
        wv[3*COLSK+tid] = Wrb[g] + Urb[g];
        wv[4*COLSK+tid] = Whw[g];
        wv[5*COLSK+tid] = Whb[g] + Uhb[g];
        wv[6*COLSK+tid] = Wgw[g];
        wv[7*COLSK+tid] = Wgb[g];
    }
    for (int idx = tid; idx < ROWS * TT; idx += NTH) {
        int r = idx >> 8, t = idx & (TT - 1);
        xsT[t * ROWS + r] = x[(rbase + r) * TT + t];
    }
    for (int idx = tid; idx < HH * ROWS; idx += NTH) hT[idx] = 0.0f;
    __syncthreads();

    // ---- per-thread constants ----
    const u64 wz2 = dupf(wv[0*COLSK+col]);
    const u64 bz2 = dupf(wv[1*COLSK+col]);
    const u64 wr2 = dupf(wv[2*COLSK+col]);
    const u64 br2 = dupf(wv[3*COLSK+col]);
    const u64 wh2 = dupf(wv[4*COLSK+col]);
    const u64 bh2 = dupf(wv[5*COLSK+col]);
    const float wgc  = wv[6*COLSK+col];
    const float wgbc = wv[7*COLSK+col];
    const float gamma = gamma_p[0];

    // GARCH scalar params (exact fp32)
    const float orw = omega_raw[0];
    const float om = ((orw > 20.0f) ? orw : log1pf(expf(orw))) + 1e-6f;
    const float av = 1.0f / (1.0f + expf(-alpha_raw[0]));
    const float bv = (1.0f / (1.0f + expf(-beta_raw[0]))) * (1.0f - av * 0.99f);
    float4 es = make_float4(1e-6f, 1e-6f, 1e-6f, 1e-6f);
    float4 ss = es;

    const uint32_t smem_u = s2u(smem);
    const uint32_t haddr  = smem_u + OFF_HT  + r0 * 4;
    const uint32_t rhaddr = smem_u + OFF_RHT + r0 * 4;
    const uint32_t waddr  = smem_u + OFF_WZR + col * 4;
    const uint32_t uhaddr = smem_u + OFF_UH  + col * 2;
    const uint32_t peer = rank ^ 1u;
    const uint32_t rh_peer = mapa32(smem_u + OFF_RHT + col * 32 + r0 * 4, peer);
    const uint32_t h_peer  = mapa32(smem_u + OFF_HT  + col * 32 + r0 * 4, peer);

    c_arrive(); c_wait();   // both CTAs initialized

    for (int t = 0; t < TT; t++) {
        // x rows r0..r0+3 for this t (pairs + scalars)
        u64 x01, x23;
        asm("ld.shared.v2.b64 {%0,%1}, [%2];" : "=l"(x01), "=l"(x23)
            : "r"(smem_u + OFF_XST + t * 32 + r0 * 4));

        // ---- phase A: z and r gates ----
        u64 az01 = bz2, az23 = bz2, ar01 = br2, ar23 = br2;
        fma2(az01, x01, wz2); fma2(az23, x23, wz2);
        fma2(ar01, x01, wr2); fma2(ar23, x23, wr2);
        #pragma unroll 8
        for (int k = 0; k < HH; k++) {
            u64 h01, h23;
            asm("ld.shared.v2.b64 {%0,%1}, [%2];" : "=l"(h01), "=l"(h23)
                : "r"(haddr + k * 32));
            uint32_t w;
            asm("ld.shared.b32 %0, [%1];" : "=r"(w) : "r"(waddr + k * 512));
            const u64 z2 = dupu(w << 16);
            const u64 r2 = dupu(w & 0xFFFF0000u);
            fma2(az01, h01, z2); fma2(az23, h23, z2);
            fma2(ar01, h01, r2); fma2(ar23, h23, r2);
        }
        const float4 hold = *(const float4*)&hT[col * ROWS + r0];
        const float2 a0 = unp(az01), a1 = unp(az23);
        const float2 b0 = unp(ar01), b1 = unp(ar23);
        const float z0 = fsig(a0.x), z1 = fsig(a0.y), z2v = fsig(a1.x), z3 = fsig(a1.y);
        const float rh0 = fsig(b0.x) * hold.x, rh1 = fsig(b0.y) * hold.y;
        const float rh2 = fsig(b1.x) * hold.z, rh3 = fsig(b1.y) * hold.w;
        *(float4*)&rhT[col * ROWS + r0] = make_float4(rh0, rh1, rh2, rh3);
        st_dsm(rh_peer + 0, rh0); st_dsm(rh_peer + 4, rh1);
        st_dsm(rh_peer + 8, rh2); st_dsm(rh_peer + 12, rh3);
        c_arrive();

        // independent work hidden under the cluster barrier:
        // GARCH update + gt + z*h_old
        const float2 xs0 = unp(x01), xs1 = unp(x23);
        float4 g;
        g.x = fmaf(av, es.x, fmaf(bv, ss.x, om));
        g.y = fmaf(av, es.y, fmaf(bv, ss.y, om));
        g.z = fmaf(av, es.z, fmaf(bv, ss.z, om));
        g.w = fmaf(av, es.w, fmaf(bv, ss.w, om));
        es = make_float4(xs0.x*xs0.x, xs0.y*xs0.y, xs1.x*xs1.x, xs1.y*xs1.y);
        ss = g;
        const float gt0 = fmaf(g.x, wgc, wgbc), gt1 = fmaf(g.y, wgc, wgbc);
        const float gt2 = fmaf(g.z, wgc, wgbc), gt3 = fmaf(g.w, wgc, wgbc);
        const float zh0 = z0 * hold.x, zh1 = z1 * hold.y;
        const float zh2 = z2v * hold.z, zh3 = z3 * hold.w;
        c_wait();   // r*h visible in both CTAs

        // ---- phase B: h_tilde ----
        u64 ah01 = bh2, ah23 = bh2;
        fma2(ah01, x01, wh2); fma2(ah23, x23, wh2);
        #pragma unroll 8
        for (int k = 0; k < HH; k++) {
            u64 rh01, rh23;
            asm("ld.shared.v2.b64 {%0,%1}, [%2];" : "=l"(rh01), "=l"(rh23)
                : "r"(rhaddr + k * 32));
            uint32_t u;
            asm("ld.shared.u16 %0, [%1];" : "=r"(u) : "r"(uhaddr + k * 256));
            const u64 uh2 = dupu(u << 16);
            fma2(ah01, rh01, uh2); fma2(ah23, rh23, uh2);
        }
        const float2 c0 = unp(ah01), c1 = unp(ah23);
        const float t0 = ftanha(c0.x), t1 = ftanha(c0.y);
        const float t2 = ftanha(c1.x), t3 = ftanha(c1.y);
        const float hn0 = ftanha(fmaf(gamma, gt0, fmaf(-z0, t0, t0) + zh0));
        const float hn1 = ftanha(fmaf(gamma, gt1, fmaf(-z1, t1, t1) + zh1));
        const float hn2 = ftanha(fmaf(gamma, gt2, fmaf(-z2v, t2, t2) + zh2));
        const float hn3 = ftanha(fmaf(gamma, gt3, fmaf(-z3, t3, t3) + zh3));
        *(float4*)&hT[col * ROWS + r0] = make_float4(hn0, hn1, hn2, hn3);
        st_dsm(h_peer + 0, hn0); st_dsm(h_peer + 4, hn1);
        st_dsm(h_peer + 8, hn2); st_dsm(h_peer + 12, hn3);
        c_arrive();
        c_wait();   // h visible -> next step
    }

    // sigma_sq output (exact fp32 path)
    if (rank == 0 && col == 0) {
        sig_out[rbase + r0 + 0] = ss.x;
        sig_out[rbase + r0 + 1] = ss.y;
        sig_out[rbase + r0 + 2] = ss.z;
        sig_out[rbase + r0 + 3] = ss.w;
    }
    // final h (own columns, coalesced across lanes)
    #pragma unroll
    for (int i = 0; i < 4; i++)
        g_h[(rbase + r0 + i) * HH + cb + col] = hT[col * ROWS + r0 + i];
}

// ---- final head: hid = relu(h@fc1+b); vol = clip(vol_base*(1+softplus(hid@fc2+b))) ----
extern "C" __global__ __launch_bounds__(256)
void garch_gru_head(const float* __restrict__ fc1w, const float* __restrict__ fc1b,
                    const float* __restrict__ fc2w, const float* __restrict__ fc2b,
                    float* __restrict__ out, int sig_off)
{
    __shared__ float hs[HH];
    __shared__ float hid[HH];
    const int row = blockIdx.x;
    const int tid = threadIdx.x;
    hs[tid] = g_h[row * HH + tid];
    __syncthreads();
    float acc = fc1b[tid];
    #pragma unroll 8
    for (int k = 0; k < HH; k++) acc = fmaf(hs[k], fc1w[k * HH + tid], acc);
    hid[tid] = fmaxf(acc, 0.0f);
    __syncthreads();
    if (tid < HORZ) {
        float u = fc2b[tid];
        #pragma unroll 8
        for (int j = 0; j < HH; j++) u = fmaf(hid[j], fc2w[j * HORZ + tid], u);
        const float sp = (u > 20.0f) ? u : log1pf(expf(u));
        const float ssq = out[sig_off + row];
        const float vb = sqrtf(ssq + 1e-8f);
        float v = vb * (1.0f + sp);
        v = fminf(fmaxf(v, 0.01f), 10.0f);
        out[row * HORZ + tid] = v;
    }
}

extern "C" void kernel_launch(void* const* d_in, const int* in_sizes, int n_in,
                              void* d_out, int out_size) {
    const float* x    = (const float*)d_in[0];
    const float* Wzw  = (const float*)d_in[1];
    const float* Wzb  = (const float*)d_in[2];
    const float* Uzw  = (const float*)d_in[3];
    const float* Uzb  = (const float*)d_in[4];
    const float* Wrw  = (const float*)d_in[5];
    const float* Wrb  = (const float*)d_in[6];
    const float* Urw  = (const float*)d_in[7];
    const float* Urb  = (const float*)d_in[8];
    const float* Whw  = (const float*)d_in[9];
    const float* Whb  = (const float*)d_in[10];
    const float* Uhw  = (const float*)d_in[11];
    const float* Uhb  = (const float*)d_in[12];
    const float* Wgw  = (const float*)d_in[13];
    const float* Wgb  = (const float*)d_in[14];
    const float* omr  = (const float*)d_in[15];
    const float* alr  = (const float*)d_in[16];
    const float* ber  = (const float*)d_in[17];
    const float* gam  = (const float*)d_in[18];
    const float* fc1w = (const float*)d_in[19];
    const float* fc1b = (const float*)d_in[20];
    const float* fc2w = (const float*)d_in[21];
    const float* fc2b = (const float*)d_in[22];
    float* out = (float*)d_out;
    const int sig_off = out_size - BB;   // vol[B,HOR] then sigma_sq[B]

    cudaFuncSetAttribute(garch_gru_recur,
                         cudaFuncAttributeMaxDynamicSharedMemorySize, SMEM_BYTES);
    garch_gru_recur<<<(BB / ROWS) * 2, NTH, SMEM_BYTES>>>(
        x, Wzw, Wzb, Uzw, Uzb, Wrw, Wrb, Urw, Urb, Whw, Whb, Uhw, Uhb, Wgw, Wgb,
        omr, alr, ber, gam, out + sig_off);
    garch_gru_head<<<BB, 256>>>(fc1w, fc1b, fc2w, fc2b, out, sig_off);
}

// round 8
// speedup vs baseline: 2.1137x; 1.8756x over previous
#include <cuda_runtime.h>
#include <cuda_bf16.h>
#include <stdint.h>

#define BB 512
#define TT 256
#define HH 256
#define HORZ 22
#define RPB 4          // batch rows per CTA
#define NTH 256        // one thread per hidden column
#define NCTA (BB / RPB)

#define SCL  16.0f
#define ISCL 0.0625f

// dynamic smem layout (bytes)
#define OFF_WZR 0          // u16 [256k][256col] : e4m3x2 (lo=Uz*16, hi=Ur*16) = 131072
#define OFF_UH  131072     // u16 [128kp][256col]: e4m3x2 (lo=Uh[2kp], hi=Uh[2kp+1])*16 = 65536
#define OFF_HT  196608     // f16 [256k][4rows]  = 2048
#define OFF_RHT 198656     // f16 [256k][4rows]  = 2048
#define OFF_XST 200704     // f32 [256t][4rows]  = 4096
#define OFF_WV  204800     // f32 [8][256]       = 8192
#define SMEM_BYTES 212992

__device__ float g_h[BB * HH];   // final hidden state scratch

__device__ __forceinline__ float ftanha(float x) {
    float y; asm("tanh.approx.f32 %0, %1;" : "=f"(y) : "f"(x)); return y;
}
__device__ __forceinline__ float fsig(float x) {
    return fmaf(0.5f, ftanha(0.5f * x), 0.5f);
}
__device__ __forceinline__ uint32_t s2u(const void* p) {
    return (uint32_t)__cvta_generic_to_shared(p);
}
__device__ __forceinline__ void hfma2(uint32_t& d, uint32_t a, uint32_t b) {
    asm("fma.rn.f16x2 %0, %1, %2, %0;" : "+r"(d) : "r"(a), "r"(b));
}
__device__ __forceinline__ uint32_t dup_lo(uint32_t a) {
    uint32_t d; asm("prmt.b32 %0, %1, %1, 0x1010;" : "=r"(d) : "r"(a)); return d;
}
__device__ __forceinline__ uint32_t dup_hi(uint32_t a) {
    uint32_t d; asm("prmt.b32 %0, %1, %1, 0x3232;" : "=r"(d) : "r"(a)); return d;
}
__device__ __forceinline__ uint32_t f8x2_to_h2(uint16_t w) {
    uint32_t d; asm("cvt.rn.f16x2.e4m3x2 %0, %1;" : "=r"(d) : "h"(w)); return d;
}
__device__ __forceinline__ float2 h2f(uint32_t p) {   // f16x2 -> (f32 lo, f32 hi)
    float2 f;
    asm("{.reg .b16 l,h; mov.b32 {l,h}, %2; cvt.f32.f16 %0, l; cvt.f32.f16 %1, h;}"
        : "=f"(f.x), "=f"(f.y) : "r"(p));
    return f;
}
__device__ __forceinline__ uint32_t f2h2(float lo, float hi) {   // pack (lo,hi) f16x2
    uint32_t d; asm("cvt.rn.f16x2.f32 %0, %1, %2;" : "=r"(d) : "f"(hi), "f"(lo)); return d;
}
__device__ __forceinline__ uint16_t f2e8x2(float lo, float hi) { // pack e4m3x2
    uint16_t d; asm("cvt.rn.satfinite.e4m3x2.f32 %0, %1, %2;" : "=h"(d) : "f"(hi), "f"(lo));
    return d;
}

extern "C" __global__ __launch_bounds__(NTH, 1)
void garch_gru_recur(const float* __restrict__ x,
                     const float* __restrict__ Wzw, const float* __restrict__ Wzb,
                     const float* __restrict__ Uzw, const float* __restrict__ Uzb,
                     const float* __restrict__ Wrw, const float* __restrict__ Wrb,
                     const float* __restrict__ Urw, const float* __restrict__ Urb,
                     const float* __restrict__ Whw, const float* __restrict__ Whb,
                     const float* __restrict__ Uhw, const float* __restrict__ Uhb,
                     const float* __restrict__ Wgw, const float* __restrict__ Wgb,
                     const float* __restrict__ omega_raw, const float* __restrict__ alpha_raw,
                     const float* __restrict__ beta_raw,  const float* __restrict__ gamma_p,
                     float* __restrict__ sig_out)
{
    extern __shared__ char smem[];
    float* xsT = (float*)(smem + OFF_XST);
    float* wv  = (float*)(smem + OFF_WV);

    const int tid = threadIdx.x;
    const int col = tid;                       // hidden column owned
    const int rbase = (int)blockIdx.x * RPB;   // batch rows of this CTA

    const uint32_t smem_u = s2u(smem);
    const uint32_t wzr_base = smem_u + OFF_WZR + col * 2;   // + k*512
    const uint32_t uh_base  = smem_u + OFF_UH  + col * 2;   // + kp*512
    const uint32_t ht_base  = smem_u + OFF_HT;              // + k*8
    const uint32_t rht_base = smem_u + OFF_RHT;             // + k*8
    const uint32_t ht_own   = smem_u + OFF_HT  + col * 8;
    const uint32_t rht_own  = smem_u + OFF_RHT + col * 8;
    const uint32_t xs_base  = smem_u + OFF_XST;

    // ---- preamble: convert weights to packed e4m3 (scaled x16) in SMEM ----
    #pragma unroll 4
    for (int k = 0; k < HH; k++) {
        const float uz = Uzw[k * HH + col] * SCL;
        const float ur = Urw[k * HH + col] * SCL;
        const uint16_t p = f2e8x2(uz, ur);    // lo=uz, hi=ur
        asm volatile("st.shared.u16 [%0], %1;" :: "r"(wzr_base + k * 512), "h"(p));
    }
    #pragma unroll 4
    for (int kp = 0; kp < HH / 2; kp++) {
        const float a = Uhw[(2 * kp)     * HH + col] * SCL;
        const float b = Uhw[(2 * kp + 1) * HH + col] * SCL;
        const uint16_t p = f2e8x2(a, b);      // lo=k even, hi=k odd
        asm volatile("st.shared.u16 [%0], %1;" :: "r"(uh_base + kp * 512), "h"(p));
    }
    {   // per-column scalars (fp32)
        wv[0*HH+col] = Wzw[col];
        wv[1*HH+col] = Wzb[col] + Uzb[col];
        wv[2*HH+col] = Wrw[col];
        wv[3*HH+col] = Wrb[col] + Urb[col];
        wv[4*HH+col] = Whw[col];
        wv[5*HH+col] = Whb[col] + Uhb[col];
        wv[6*HH+col] = Wgw[col];
        wv[7*HH+col] = Wgb[col];
    }
    // x tile (fp32, exact: feeds GARCH)
    for (int idx = tid; idx < RPB * TT; idx += NTH) {
        int r = idx >> 8, t = idx & (TT - 1);
        xsT[t * RPB + r] = x[(rbase + r) * TT + t];
    }
    // zero h (f16)
    asm volatile("st.shared.v2.b32 [%0], {%1,%1};" :: "r"(ht_own), "r"(0u));
    __syncthreads();

    // ---- per-thread constants ----
    const float wzc = wv[0*HH+col], bzc = wv[1*HH+col];
    const float wrc = wv[2*HH+col], brc = wv[3*HH+col];
    const float whc = wv[4*HH+col], bhc = wv[5*HH+col];
    const float wgc = wv[6*HH+col], wgbc= wv[7*HH+col];
    const float gamma = gamma_p[0];

    // GARCH scalar params (exact fp32; redundantly computed by all threads)
    const float orw = omega_raw[0];
    const float om = ((orw > 20.0f) ? orw : log1pf(expf(orw))) + 1e-6f;
    const float av = 1.0f / (1.0f + expf(-alpha_raw[0]));
    const float bv = (1.0f / (1.0f + expf(-beta_raw[0]))) * (1.0f - av * 0.99f);
    float4 es = make_float4(1e-6f, 1e-6f, 1e-6f, 1e-6f);
    float4 ss = es;

    // own h kept in fp32 registers
    float h0 = 0.0f, h1 = 0.0f, h2 = 0.0f, h3 = 0.0f;

    for (int t = 0; t < TT; t++) {
        float4 xv;
        asm("ld.shared.v4.f32 {%0,%1,%2,%3}, [%4];"
            : "=f"(xv.x), "=f"(xv.y), "=f"(xv.z), "=f"(xv.w)
            : "r"(xs_base + t * 16));

        // ---- phase A: z and r gate accumulation (f16x2 over row pairs) ----
        uint32_t az01 = 0u, az23 = 0u, ar01 = 0u, ar23 = 0u;
        #pragma unroll 8
        for (int k = 0; k < HH; k++) {
            uint32_t g01, g23;
            asm("ld.shared.v2.b32 {%0,%1}, [%2];" : "=r"(g01), "=r"(g23)
                : "r"(ht_base + k * 8));
            uint16_t w;
            asm("ld.shared.u16 %0, [%1];" : "=h"(w) : "r"(wzr_base + k * 512));
            const uint32_t wzr = f8x2_to_h2(w);
            const uint32_t z2 = dup_lo(wzr);
            const uint32_t r2 = dup_hi(wzr);
            hfma2(az01, g01, z2); hfma2(az23, g23, z2);
            hfma2(ar01, g01, r2); hfma2(ar23, g23, r2);
        }
        const float2 a0 = h2f(az01), a1 = h2f(az23);
        const float2 b0 = h2f(ar01), b1 = h2f(ar23);
        const float z0 = fsig(fmaf(a0.x, ISCL, fmaf(xv.x, wzc, bzc)));
        const float z1 = fsig(fmaf(a0.y, ISCL, fmaf(xv.y, wzc, bzc)));
        const float z2v= fsig(fmaf(a1.x, ISCL, fmaf(xv.z, wzc, bzc)));
        const float z3 = fsig(fmaf(a1.y, ISCL, fmaf(xv.w, wzc, bzc)));
        const float rh0 = fsig(fmaf(b0.x, ISCL, fmaf(xv.x, wrc, brc))) * h0;
        const float rh1 = fsig(fmaf(b0.y, ISCL, fmaf(xv.y, wrc, brc))) * h1;
        const float rh2 = fsig(fmaf(b1.x, ISCL, fmaf(xv.z, wrc, brc))) * h2;
        const float rh3 = fsig(fmaf(b1.y, ISCL, fmaf(xv.w, wrc, brc))) * h3;
        {
            const uint32_t p01 = f2h2(rh0, rh1), p23 = f2h2(rh2, rh3);
            asm volatile("st.shared.v2.b32 [%0], {%1,%2};"
                         :: "r"(rht_own), "r"(p01), "r"(p23));
        }

        // independent work before the barrier: GARCH + gt + z*h_old
        float4 g;
        g.x = fmaf(av, es.x, fmaf(bv, ss.x, om));
        g.y = fmaf(av, es.y, fmaf(bv, ss.y, om));
        g.z = fmaf(av, es.z, fmaf(bv, ss.z, om));
        g.w = fmaf(av, es.w, fmaf(bv, ss.w, om));
        es = make_float4(xv.x*xv.x, xv.y*xv.y, xv.z*xv.z, xv.w*xv.w);
        ss = g;
        const float gt0 = fmaf(g.x, wgc, wgbc), gt1 = fmaf(g.y, wgc, wgbc);
        const float gt2 = fmaf(g.z, wgc, wgbc), gt3 = fmaf(g.w, wgc, wgbc);
        const float zh0 = z0 * h0, zh1 = z1 * h1, zh2 = z2v * h2, zh3 = z3 * h3;
        __syncthreads();   // r*h tile complete

        // ---- phase B: h_tilde accumulation (k-pairs) ----
        uint32_t ah01 = 0u, ah23 = 0u;
        #pragma unroll 8
        for (int kp = 0; kp < HH / 2; kp++) {
            uint32_t ra01, ra23, rb01, rb23;
            asm("ld.shared.v4.b32 {%0,%1,%2,%3}, [%4];"
                : "=r"(ra01), "=r"(ra23), "=r"(rb01), "=r"(rb23)
                : "r"(rht_base + kp * 16));
            uint16_t w;
            asm("ld.shared.u16 %0, [%1];" : "=h"(w) : "r"(uh_base + kp * 512));
            const uint32_t uh2 = f8x2_to_h2(w);
            const uint32_t ulo = dup_lo(uh2);
            const uint32_t uhi = dup_hi(uh2);
            hfma2(ah01, ra01, ulo); hfma2(ah23, ra23, ulo);
            hfma2(ah01, rb01, uhi); hfma2(ah23, rb23, uhi);
        }
        const float2 c0 = h2f(ah01), c1 = h2f(ah23);
        const float t0 = ftanha(fmaf(c0.x, ISCL, fmaf(xv.x, whc, bhc)));
        const float t1 = ftanha(fmaf(c0.y, ISCL, fmaf(xv.y, whc, bhc)));
        const float t2 = ftanha(fmaf(c1.x, ISCL, fmaf(xv.z, whc, bhc)));
        const float t3 = ftanha(fmaf(c1.y, ISCL, fmaf(xv.w, whc, bhc)));
        h0 = ftanha(fmaf(gamma, gt0, fmaf(-z0, t0, t0) + zh0));
        h1 = ftanha(fmaf(gamma, gt1, fmaf(-z1, t1, t1) + zh1));
        h2 = ftanha(fmaf(gamma, gt2, fmaf(-z2v, t2, t2) + zh2));
        h3 = ftanha(fmaf(gamma, gt3, fmaf(-z3, t3, t3) + zh3));
        {
            const uint32_t p01 = f2h2(h0, h1), p23 = f2h2(h2, h3);
            asm volatile("st.shared.v2.b32 [%0], {%1,%2};"
                         :: "r"(ht_own), "r"(p01), "r"(p23));
        }
        __syncthreads();   // h tile complete -> next step
    }

    // sigma_sq output (exact fp32 path)
    if (tid == 0) {
        sig_out[rbase + 0] = ss.x;
        sig_out[rbase + 1] = ss.y;
        sig_out[rbase + 2] = ss.z;
        sig_out[rbase + 3] = ss.w;
    }
    // final h (fp32 registers; coalesced across lanes)
    g_h[(rbase + 0) * HH + col] = h0;
    g_h[(rbase + 1) * HH + col] = h1;
    g_h[(rbase + 2) * HH + col] = h2;
    g_h[(rbase + 3) * HH + col] = h3;
}

// ---- final head: hid = relu(h@fc1+b); vol = clip(vol_base*(1+softplus(hid@fc2+b))) ----
extern "C" __global__ __launch_bounds__(256)
void garch_gru_head(const float* __restrict__ fc1w, const float* __restrict__ fc1b,
                    const float* __restrict__ fc2w, const float* __restrict__ fc2b,
                    float* __restrict__ out, int sig_off)
{
    __shared__ float hs[HH];
    __shared__ float hid[HH];
    const int row = blockIdx.x;
    const int tid = threadIdx.x;
    hs[tid] = g_h[row * HH + tid];
    __syncthreads();
    float acc = fc1b[tid];
    #pragma unroll 8
    for (int k = 0; k < HH; k++) acc = fmaf(hs[k], fc1w[k * HH + tid], acc);
    hid[tid] = fmaxf(acc, 0.0f);
    __syncthreads();
    if (tid < HORZ) {
        float u = fc2b[tid];
        #pragma unroll 8
        for (int j = 0; j < HH; j++) u = fmaf(hid[j], fc2w[j * HORZ + tid], u);
        const float sp = (u > 20.0f) ? u : log1pf(expf(u));
        const float ssq = out[sig_off + row];
        const float vb = sqrtf(ssq + 1e-8f);
        float v = vb * (1.0f + sp);
        v = fminf(fmaxf(v, 0.01f), 10.0f);
        out[row * HORZ + tid] = v;
    }
}

extern "C" void kernel_launch(void* const* d_in, const int* in_sizes, int n_in,
                              void* d_out, int out_size) {
    const float* x    = (const float*)d_in[0];
    const float* Wzw  = (const float*)d_in[1];
    const float* Wzb  = (const float*)d_in[2];
    const float* Uzw  = (const float*)d_in[3];
    const float* Uzb  = (const float*)d_in[4];
    const float* Wrw  = (const float*)d_in[5];
    const float* Wrb  = (const float*)d_in[6];
    const float* Urw  = (const float*)d_in[7];
    const float* Urb  = (const float*)d_in[8];
    const float* Whw  = (const float*)d_in[9];
    const float* Whb  = (const float*)d_in[10];
    const float* Uhw  = (const float*)d_in[11];
    const float* Uhb  = (const float*)d_in[12];
    const float* Wgw  = (const float*)d_in[13];
    const float* Wgb  = (const float*)d_in[14];
    const float* omr  = (const float*)d_in[15];
    const float* alr  = (const float*)d_in[16];
    const float* ber  = (const float*)d_in[17];
    const float* gam  = (const float*)d_in[18];
    const float* fc1w = (const float*)d_in[19];
    const float* fc1b = (const float*)d_in[20];
    const float* fc2w = (const float*)d_in[21];
    const float* fc2b = (const float*)d_in[22];
    float* out = (float*)d_out;
    const int sig_off = out_size - BB;   // vol[B,HOR] then sigma_sq[B]

    cudaFuncSetAttribute(garch_gru_recur,
                         cudaFuncAttributeMaxDynamicSharedMemorySize, SMEM_BYTES);
    garch_gru_recur<<<NCTA, NTH, SMEM_BYTES>>>(
        x, Wzw, Wzb, Uzw, Uzb, Wrw, Wrb, Urw, Urb, Whw, Whb, Uhw, Uhb, Wgw, Wgb,
        omr, alr, ber, gam, out + sig_off);
    garch_gru_head<<<BB, 256>>>(fc1w, fc1b, fc2w, fc2b, out, sig_off);
}